// round 13
// baseline (speedup 1.0000x reference)
#include <cuda_runtime.h>
#include <cstdint>
#include <math.h>

// ---------------------------------------------------------------------------
// ClassicalMappedQRNN fast path (alpha=beta=pi/2). B=8192 chains, S=4096.
// Block = 64 threads = 2 warps (SMSP 0,1), 128 blocks (1/SM).
//   warp 0: serial recurrence, TWO chains per thread (lane, lane+32)
//   warp 1: trig producer for the same 64 chains (2 rows/thread)
// WHY 2 chains/thread: R8/R10/R12 showed the serial warp stall-bound at
// ~68 cyc/step (issue 29%) with identical SASS regardless of source-level
// scheduling — ptxas re-serializes one dependency web. Two INDEPENDENT
// chains interleave in the scheduler by construction: chain B's ops fill
// chain A's rsq/LDS stalls. Bound -> ~30 cyc/step (fma-pipe).
// Producer streams per step float4 (C, S, c, -):
//   C = sqrt2*cos(phi/2) = sqrt(1+r),  S = sqrt2*sin(phi/2) = x r/sqrt(1+r),
//   r = rsqrt(1+x^2),  c_t = 2(C_{t-1}C_t + S_{t-1}S_t)   [input-only]
// Serial recurrence (G, K = sqrt2/||G||, v=(C,-S,S,C), ||v||=2):
//   d_t = c_t - 2K_{t-2}(C_t gm + S_t bt),  gm,bt = butterflies of G_{t-2}
//   m_t = 4 + K_{t-1} d_t;  K_t = rsqrt(m_t);  G_t = K_{t-1} W(G_{t-1}) + v_t
// Parity queues (t&1) avoid rotation movs. Exact renorm every chunk.
// ---------------------------------------------------------------------------

#define CHUNK  16
#define TPB    64
#define GUARD4 4.000021f

__device__ __forceinline__ float rsqa(float x) {
    float y; asm("rsqrt.approx.f32 %0, %1;" : "=f"(y) : "f"(x)); return y;
}
__device__ __forceinline__ void bar64() {
    asm volatile("bar.sync 0, 64;" ::: "memory");
}

// [buf(2)][t(16)][chain(64)] float4 = 32768 bytes (static)
__shared__ float4 sb4[2 * CHUNK * 64];

// ---------------- serial side ----------------
struct SState {
    float g0, g1, g2, g3, K;
    float qg[2], qb[2], qK2[2];   // butterflies + doubled K from step t-2
};

__device__ __forceinline__ void s_init(SState& s, float4 f) {
    s.g0 = f.x; s.g1 = -f.y; s.g2 = f.y; s.g3 = f.x;  // G0 = v0
    s.K  = 0.70710678118654752f;
    s.qg[0] = 0.0f; s.qb[0] = 0.0f;                    // butterflies(G0) = 0
    s.qK2[0] = 1.41421356237309505f;
}

__device__ __forceinline__ void s_tail(SState& s, float4 f, float Kn, int par,
                                       float w0, float w1, float w2, float w3) {
    float n0 = fmaf(s.K, w0,  f.x);
    float n1 = fmaf(s.K, w1, -f.y);
    float n2 = fmaf(s.K, w2,  f.y);
    float n3 = fmaf(s.K, w3,  f.x);
    s.qg[par]  = n1 + n2;
    s.qb[par]  = n0 - n3;
    s.qK2[par] = Kn + Kn;
    s.g0 = n0; s.g1 = n1; s.g2 = n2; s.g3 = n3; s.K = Kn;
}

__device__ __forceinline__ void s_direct(SState& s, float4 f, int par) {
    float w0 = s.g0 - s.g1, w1 = s.g0 + s.g1;
    float w2 = s.g2 + s.g3, w3 = s.g3 - s.g2;
    float d  = fmaf(f.y, w2 - w1, f.x * (w0 + w3));
    float m  = fmaf(s.K, d, GUARD4);
    float Kn = rsqa(m);
    s_tail(s, f, Kn, par, w0, w1, w2, w3);
}

__device__ __forceinline__ void s_step(SState& s, float4 f, int par) {
    float up = fmaf(f.y, s.qb[par], f.x * s.qg[par]);  // C*gm + S*bt
    float z  = fmaf(-s.qK2[par], up, f.z);             // d_t (off-chain)
    float m  = fmaf(s.K, z, GUARD4);
    float Kn = rsqa(m);                                // 20-cyc chain
    float w0 = s.g0 - s.g1, w1 = s.g0 + s.g1;
    float w2 = s.g2 + s.g3, w3 = s.g3 - s.g2;
    s_tail(s, f, Kn, par, w0, w1, w2, w3);
}

__device__ __forceinline__ void s_renorm(SState& s) {
    float ss = (s.g0 * s.g0 + s.g1 * s.g1) + (s.g2 * s.g2 + s.g3 * s.g3);
    s.K = rsqa(0.5f * ss);                             // exact sqrt2/||G||
}

// Consume one chunk for BOTH chains, interleaved (the ILP source).
template <bool FIRST>
__device__ __forceinline__ void consume2(SState& a, SState& b,
                                         const float4* base, int lane) {
    const float4* pa = base + lane;        // chain A: rows stride 64
    const float4* pb = base + lane + 32;   // chain B
    float4 fa = pa[0], fb = pb[0];
    #pragma unroll
    for (int t = 0; t < CHUNK; t++) {
        int tn = (t + 1 < CHUNK) ? t + 1 : t;
        float4 fan = pa[tn * 64];
        float4 fbn = pb[tn * 64];
        if (FIRST && t == 0)      { s_init(a, fa);      s_init(b, fb); }
        else if (FIRST && t == 1) { s_direct(a, fa, 1); s_direct(b, fb, 1); }
        else                      { s_step(a, fa, t & 1); s_step(b, fb, t & 1); }
        fa = fan; fb = fbn;
    }
    s_renorm(a);
    s_renorm(b);
}

// ---------------- producer side ----------------
struct PReg { float4 a[CHUNK / 4]; };

__device__ __forceinline__ void p_load(PReg& r, const float* __restrict__ row,
                                       int c) {
    const float4* p = reinterpret_cast<const float4*>(row + c * CHUNK);
    #pragma unroll
    for (int i = 0; i < CHUNK / 4; i++) r.a[i] = __ldg(p + i);
}

__device__ __forceinline__ void p_emit(float x, float& Cp, float& Sp,
                                       float4* dst) {
    float tq = fmaf(x, x, 1.0f);
    float r  = rsqa(tq);
    float e  = r + 1.0f;
    float q  = rsqa(e);
    float C  = e * q;                      // sqrt2 cos(phi/2)
    float S  = (x * r) * q;                // sqrt2 sin(phi/2)
    float cc = fmaf(S, Sp, C * Cp);
    float c2 = cc + cc;                    // 2(CC'+SS')
    *dst = make_float4(C, S, c2, 0.0f);
    Cp = C; Sp = S;
}

// Fill one chunk for BOTH chains, interleaved (fills MUFU latency).
__device__ __forceinline__ void p_chunk2(const PReg& rA, const PReg& rB,
                                         float& CpA, float& SpA,
                                         float& CpB, float& SpB,
                                         float4* wbA, float4* wbB) {
    #pragma unroll
    for (int i = 0; i < CHUNK / 4; i++) {
        p_emit(rA.a[i].x, CpA, SpA, wbA + (i * 4 + 0) * 64);
        p_emit(rB.a[i].x, CpB, SpB, wbB + (i * 4 + 0) * 64);
        p_emit(rA.a[i].y, CpA, SpA, wbA + (i * 4 + 1) * 64);
        p_emit(rB.a[i].y, CpB, SpB, wbB + (i * 4 + 1) * 64);
        p_emit(rA.a[i].z, CpA, SpA, wbA + (i * 4 + 2) * 64);
        p_emit(rB.a[i].z, CpB, SpB, wbB + (i * 4 + 2) * 64);
        p_emit(rA.a[i].w, CpA, SpA, wbA + (i * 4 + 3) * 64);
        p_emit(rB.a[i].w, CpB, SpB, wbB + (i * 4 + 3) * 64);
    }
}

// ---------------- fallback ----------------
__device__ void run_simple(const float* __restrict__ xrow, float* __restrict__ outb,
                           int S, float ca, float sa, float cb, float sb) {
    float h0 = 0.f, h1 = 0.f, h2 = 0.f, h3 = 0.f;
    for (int t = 0; t < S; t++) {
        float xv = xrow[t];
        float phi = atanf(xv);
        float c = cosf(0.5f * phi);
        float s = sinf(0.5f * phi);
        float u0 = ca * c + cb * h0 - sb * h1;
        float u1 = -(sa * s) + sb * h0 + cb * h1;
        float u2 = ca * s + cb * h2 + sb * h3;
        float u3 = sa * c - sb * h2 + cb * h3;
        float ss = u0*u0 + u1*u1 + u2*u2 + u3*u3;
        float rn = rsqrtf(ss);
        h0 = u0 * rn; h1 = u1 * rn; h2 = u2 * rn; h3 = u3 * rn;
    }
    *outb = (h0*h0 + h1*h1) - (h2*h2 + h3*h3);
}

// ---------------- kernel ----------------
__global__ void __launch_bounds__(TPB, 1)
qrnn_kernel(const float* __restrict__ x, const float* __restrict__ pa,
            const float* __restrict__ pb, float* __restrict__ out, int B, int S) {
    int tid  = threadIdx.x;
    int wid  = tid >> 5;
    int lane = tid & 31;

    float alpha = __ldg(pa);
    float beta  = __ldg(pb);
    const float PIO2 = 1.57079632679489662f;
    bool fast = (fabsf(alpha - PIO2) < 1e-5f) && (fabsf(beta - PIO2) < 1e-5f)
                && (S % 64 == 0) && (S >= 128) && (B % 64 == 0);

    if (!fast) {
        int b = blockIdx.x * TPB + tid;
        if (b < B) {
            float ca = cosf(0.5f * alpha), sa = sinf(0.5f * alpha);
            float cb = cosf(0.5f * beta),  sb = sinf(0.5f * beta);
            run_simple(x + (size_t)b * S, out + b, S, ca, sa, cb, sb);
        }
        return;
    }

    const int nch = S / CHUNK;            // even
    int cA = blockIdx.x * 64 + lane;      // chain A
    int cB = cA + 32;                     // chain B

    if (wid == 0) {
        // ------------- serial role: 2 chains per thread -------------
        SState sa_, sb_;
        bar64();                                   // chunk 0 ready
        #pragma unroll 1
        for (int c = 0; c < nch; c++) {
            const float4* base = sb4 + (c & 1) * (CHUNK * 64);
            if (c == 0) consume2<true >(sa_, sb_, base, lane);
            else        consume2<false>(sa_, sb_, base, lane);
            bar64();
        }
        float a01 = sa_.g0 * sa_.g0 + sa_.g1 * sa_.g1;
        float a23 = sa_.g2 * sa_.g2 + sa_.g3 * sa_.g3;
        out[cA] = (a01 - a23) / (a01 + a23);
        float b01 = sb_.g0 * sb_.g0 + sb_.g1 * sb_.g1;
        float b23 = sb_.g2 * sb_.g2 + sb_.g3 * sb_.g3;
        out[cB] = (b01 - b23) / (b01 + b23);
    } else {
        // ------------- producer role: 2 rows per thread -------------
        const float* rowA = x + (size_t)cA * S;
        const float* rowB = x + (size_t)cB * S;
        float4* wbA0 = sb4 + lane;
        float4* wbB0 = sb4 + lane + 32;
        float4* wbA1 = sb4 + CHUNK * 64 + lane;
        float4* wbB1 = sb4 + CHUNK * 64 + lane + 32;

        float CpA = 0.0f, SpA = 0.0f, CpB = 0.0f, SpB = 0.0f;
        PReg raA, raB, rbA, rbB;
        p_load(raA, rowA, 0);
        p_load(raB, rowB, 0);

        #pragma unroll 1
        for (int c = 0; c < nch; c += 2) {
            int c1 = (c + 1 < nch) ? c + 1 : c;
            p_load(rbA, rowA, c1);
            p_load(rbB, rowB, c1);
            p_chunk2(raA, raB, CpA, SpA, CpB, SpB, wbA0, wbB0);  // chunk c
            bar64();
            int c2 = (c + 2 < nch) ? c + 2 : c1;
            p_load(raA, rowA, c2);
            p_load(raB, rowB, c2);
            p_chunk2(rbA, rbB, CpA, SpA, CpB, SpB, wbA1, wbB1);  // chunk c+1
            bar64();
        }
        bar64();                                   // match serial's final wait
    }
}

extern "C" void kernel_launch(void* const* d_in, const int* in_sizes, int n_in,
                              void* d_out, int out_size) {
    const float* x  = (const float*)d_in[0];
    const float* pa = (const float*)d_in[1];
    const float* pb = (const float*)d_in[2];
    float* out = (float*)d_out;

    int B = out_size;                 // 8192
    int S = in_sizes[0] / B;          // 4096

    int grid = (B + 63) / 64;         // 128 blocks x 64 threads, 1 block/SM
    qrnn_kernel<<<grid, TPB>>>(x, pa, pb, out, B, S);
}

// round 14
// speedup vs baseline: 1.6787x; 1.6787x over previous
#include <cuda_runtime.h>
#include <cstdint>
#include <math.h>

// ---------------------------------------------------------------------------
// ClassicalMappedQRNN fast path (alpha=beta=pi/2). B=8192 chains, S=4096.
// WARP-SPECIALIZED (R8 infra) + FUSED DOUBLE-STEP (R6 math).
//   block = 128 thr = 4 warps: 0,1 serial (1 chain/thread); 2,3 producers.
// Producer streams per step float4 (C, S, cc, P):
//   C = sqrt2*cos(phi/2) = sqrt(1+r),  S = sqrt2*sin(phi/2) = x r/sqrt(1+r)
//   cc_t = C_{t-1}C_t + S_{t-1}S_t   (input-only),  P = C+S
// Consumer fused pair (R^2 = 2J, J(g)=(-g1,g0,g3,-g2); K = sqrt2/||G||):
//   a = g0-g1-g2+g3; b = g2+g3-g0-g1; d1 = C a + S b
//   m1 = 4 + K1 d1;  K2 = rsqrt(m1)
//   e = C2(g1+g2) + S2(g0-g3);  hf = cc - K1 e
//   m2 = 4 + 2K2 hf; K3 = rsqrt(m2)
//   G' = 2K2K1 J(G) + K2 (P,M,P,M) + (C2,-S2,S2,C2),  M = C-S
// ~29 fma-class/pair (14.5/step) with 29 instrs of slack between chain ops —
// attacks BOTH the fma-pipe floor and the in-order-issue stall exposure that
// capped R8 (68 cyc/step) and sank R13 (2 chains/thread doubled pipe load).
// ---------------------------------------------------------------------------

#define CHUNK  16
#define TPB    128
#define GUARD4 4.000021f

__device__ __forceinline__ float rsqa(float x) {
    float y; asm("rsqrt.approx.f32 %0, %1;" : "=f"(y) : "f"(x)); return y;
}
__device__ __forceinline__ void barp(int id) {
    asm volatile("bar.sync %0, 64;" :: "r"(id) : "memory");
}

// [pair(2)][buf(2)][t(16)][lane(32)] float4 = 32768 bytes (static)
__shared__ float4 sb4[2 * 2 * CHUNK * 32];

// ---------------- serial side ----------------
struct SState { float g0, g1, g2, g3, K; };

__device__ __forceinline__ void s_init(SState& s, float4 f) {
    s.g0 = f.x; s.g1 = -f.y; s.g2 = f.y; s.g3 = f.x;   // G0 = v0 = (C,-S,S,C)
    s.K  = 0.70710678118654752f;                        // sqrt2/||G0||, ||G0||=2
}

// single direct step (chunk 0, t=1 only)
__device__ __forceinline__ void s_direct(SState& s, float4 f) {
    float w0 = s.g0 - s.g1, w1 = s.g0 + s.g1;
    float w2 = s.g2 + s.g3, w3 = s.g3 - s.g2;
    float d  = fmaf(f.y, w2 - w1, f.x * (w0 + w3));
    float m  = fmaf(s.K, d, GUARD4);
    float Kn = rsqa(m);
    float n0 = fmaf(s.K, w0,  f.x);
    float n1 = fmaf(s.K, w1, -f.y);
    float n2 = fmaf(s.K, w2,  f.y);
    float n3 = fmaf(s.K, w3,  f.x);
    s.g0 = n0; s.g1 = n1; s.g2 = n2; s.g3 = n3; s.K = Kn;
}

// fused pair: steps (t, t+1). fa=(C,S,cc_t,P), fb=(C2,S2,cc[t,t+1],P2)
__device__ __forceinline__ void s_pair(SState& s, float4 fa, float4 fb) {
    float C = fa.x, Sx = fa.y, P = fa.w;
    float C2 = fb.x, S2 = fb.y, cc = fb.z;
    float M  = C - Sx;
    // d1 from state butterflies
    float w01 = s.g0 - s.g1, w23 = s.g2 - s.g3;
    float p01 = s.g0 + s.g1, p23 = s.g2 + s.g3;
    float a = w01 - w23;
    float b = p23 - p01;
    float d1 = fmaf(Sx, b, C * a);
    float m1 = fmaf(s.K, d1, GUARD4);
    float K2 = rsqa(m1);                              // chain
    // d2 path (old state + input-only cc)
    float gam = s.g1 + s.g2;
    float bet = s.g0 - s.g3;
    float e   = fmaf(S2, bet, C2 * gam);
    float hf  = fmaf(-s.K, e, cc);
    float K22 = K2 + K2;
    float m2  = fmaf(K22, hf, GUARD4);
    float K3  = rsqa(m2);                             // chain
    // fused state update
    float KK2 = K22 * s.K;                            // 2 K2 K1
    float KP  = K2 * P;
    float KM  = K2 * M;
    float n0 = fmaf(-KK2, s.g1, KP + C2);
    float n2 = fmaf( KK2, s.g3, KP + S2);
    float n1 = fmaf( KK2, s.g0, KM - S2);
    float n3 = fmaf(-KK2, s.g2, KM + C2);
    s.g0 = n0; s.g1 = n1; s.g2 = n2; s.g3 = n3; s.K = K3;
}

__device__ __forceinline__ void s_renorm(SState& s) {
    float ss = (s.g0 * s.g0 + s.g1 * s.g1) + (s.g2 * s.g2 + s.g3 * s.g3);
    s.K = rsqa(0.5f * ss);                            // exact sqrt2/||G||
}

template <bool FIRST>
__device__ __forceinline__ void consume_chunk(SState& s, const float4* sb) {
    if (FIRST) {
        s_init(s, sb[0]);
        s_direct(s, sb[32]);
        float4 fa = sb[2 * 32], fb = sb[3 * 32];
        #pragma unroll
        for (int p = 1; p < CHUNK / 2; p++) {
            int pn = (p + 1 < CHUNK / 2) ? p + 1 : p;
            float4 fan = sb[(2 * pn) * 32];
            float4 fbn = sb[(2 * pn + 1) * 32];
            s_pair(s, fa, fb);
            fa = fan; fb = fbn;
        }
    } else {
        float4 fa = sb[0], fb = sb[32];
        #pragma unroll
        for (int p = 0; p < CHUNK / 2; p++) {
            int pn = (p + 1 < CHUNK / 2) ? p + 1 : p;
            float4 fan = sb[(2 * pn) * 32];
            float4 fbn = sb[(2 * pn + 1) * 32];
            s_pair(s, fa, fb);
            fa = fan; fb = fbn;
        }
    }
    s_renorm(s);   // exact rescale every 16 steps: kills approx-rsqrt drift
}

// ---------------- producer side ----------------
struct PReg { float4 a[CHUNK / 4]; };

__device__ __forceinline__ void p_load(PReg& r, const float* __restrict__ xrow,
                                       int c) {
    const float4* p = reinterpret_cast<const float4*>(xrow + c * CHUNK);
    #pragma unroll
    for (int i = 0; i < CHUNK / 4; i++) r.a[i] = __ldg(p + i);
}

__device__ __forceinline__ void p_emit(float x, float& Cp, float& Sp,
                                       float4* dst) {
    float tq = fmaf(x, x, 1.0f);
    float r  = rsqa(tq);
    float e  = r + 1.0f;
    float q  = rsqa(e);
    float C  = e * q;                      // sqrt2 cos(phi/2)
    float S  = (x * r) * q;                // sqrt2 sin(phi/2)
    float cc = fmaf(S, Sp, C * Cp);        // C_{t-1}C_t + S_{t-1}S_t
    *dst = make_float4(C, S, cc, C + S);
    Cp = C; Sp = S;
}

__device__ __forceinline__ void p_chunk(const PReg& r, float& Cp, float& Sp,
                                        float4* wb) {
    #pragma unroll
    for (int i = 0; i < CHUNK / 4; i++) {
        p_emit(r.a[i].x, Cp, Sp, wb + (i * 4 + 0) * 32);
        p_emit(r.a[i].y, Cp, Sp, wb + (i * 4 + 1) * 32);
        p_emit(r.a[i].z, Cp, Sp, wb + (i * 4 + 2) * 32);
        p_emit(r.a[i].w, Cp, Sp, wb + (i * 4 + 3) * 32);
    }
}

// ---------------- fallback ----------------
__device__ void run_simple(const float* __restrict__ xrow, float* __restrict__ outb,
                           int S, float ca, float sa, float cb, float sb) {
    float h0 = 0.f, h1 = 0.f, h2 = 0.f, h3 = 0.f;
    for (int t = 0; t < S; t++) {
        float xv = xrow[t];
        float phi = atanf(xv);
        float c = cosf(0.5f * phi);
        float s = sinf(0.5f * phi);
        float u0 = ca * c + cb * h0 - sb * h1;
        float u1 = -(sa * s) + sb * h0 + cb * h1;
        float u2 = ca * s + cb * h2 + sb * h3;
        float u3 = sa * c - sb * h2 + cb * h3;
        float ss = u0*u0 + u1*u1 + u2*u2 + u3*u3;
        float rn = rsqrtf(ss);
        h0 = u0 * rn; h1 = u1 * rn; h2 = u2 * rn; h3 = u3 * rn;
    }
    *outb = (h0*h0 + h1*h1) - (h2*h2 + h3*h3);
}

// ---------------- kernel ----------------
__global__ void __launch_bounds__(TPB, 1)
qrnn_kernel(const float* __restrict__ x, const float* __restrict__ pa,
            const float* __restrict__ pb, float* __restrict__ out, int B, int S) {
    int tid  = threadIdx.x;
    int wid  = tid >> 5;
    int lane = tid & 31;

    float alpha = __ldg(pa);
    float beta  = __ldg(pb);
    const float PIO2 = 1.57079632679489662f;
    bool fast = (fabsf(alpha - PIO2) < 1e-5f) && (fabsf(beta - PIO2) < 1e-5f)
                && (S % 64 == 0) && (S >= 128);

    if (!fast) {
        if (tid < 64) {
            int b = blockIdx.x * 64 + tid;
            if (b < B) {
                float ca = cosf(0.5f * alpha), sa = sinf(0.5f * alpha);
                float cb = cosf(0.5f * beta),  sb = sinf(0.5f * beta);
                run_simple(x + (size_t)b * S, out + b, S, ca, sa, cb, sb);
            }
        }
        return;
    }

    const int nch = S / CHUNK;        // multiple of 4 (S % 64 == 0)

    if (wid < 2) {
        // ------------- serial role -------------
        int w  = wid;
        int b  = blockIdx.x * 64 + w * 32 + lane;
        int id = 1 + w;
        const float4* rb0 = sb4 + (w * 2 + 0) * (CHUNK * 32) + lane;
        const float4* rb1 = sb4 + (w * 2 + 1) * (CHUNK * 32) + lane;

        SState s;
        barp(id);                                  // wait: chunk 0 ready
        #pragma unroll 1
        for (int c = 0; c < nch; c++) {
            if (c == 0) consume_chunk<true >(s, rb0);
            else        consume_chunk<false>(s, (c & 1) ? rb1 : rb0);
            barp(id);
        }

        if (b < B) {
            float a01 = s.g0 * s.g0 + s.g1 * s.g1;
            float a23 = s.g2 * s.g2 + s.g3 * s.g3;
            out[b] = (a01 - a23) / (a01 + a23);
        }
    } else {
        // ------------- producer role -------------
        int w  = wid - 2;
        int b  = blockIdx.x * 64 + w * 32 + lane;
        if (b >= B) b = B - 1;                     // clamp (keeps bars uniform)
        int id = 1 + w;
        const float* xrow = x + (size_t)b * S;
        float4* wb0 = sb4 + (w * 2 + 0) * (CHUNK * 32) + lane;
        float4* wb1 = sb4 + (w * 2 + 1) * (CHUNK * 32) + lane;

        float Cp = 0.0f, Sp = 0.0f;
        PReg ra, rbuf;
        p_load(ra, xrow, 0);

        #pragma unroll 1
        for (int c = 0; c < nch; c += 2) {
            int c1 = (c + 1 < nch) ? c + 1 : c;
            p_load(rbuf, xrow, c1);
            p_chunk(ra, Cp, Sp, wb0);              // chunk c   -> buf 0
            barp(id);
            int c2 = (c + 2 < nch) ? c + 2 : c1;
            p_load(ra, xrow, c2);
            p_chunk(rbuf, Cp, Sp, wb1);            // chunk c+1 -> buf 1
            barp(id);
        }
        barp(id);                                  // match serial's final wait
    }
}

extern "C" void kernel_launch(void* const* d_in, const int* in_sizes, int n_in,
                              void* d_out, int out_size) {
    const float* x  = (const float*)d_in[0];
    const float* pa = (const float*)d_in[1];
    const float* pb = (const float*)d_in[2];
    float* out = (float*)d_out;

    int B = out_size;                 // 8192
    int S = in_sizes[0] / B;          // 4096

    int grid = (B + 63) / 64;         // 128 blocks x 128 threads, 1 block/SM
    qrnn_kernel<<<grid, TPB>>>(x, pa, pb, out, B, S);
}